// round 10
// baseline (speedup 1.0000x reference)
#include <cuda_runtime.h>
#include <cstdint>

// Problem constants (fixed by the reference: B=8, H=16, L=512, D=64)
#define BH   128
#define LSEQ 512
#define DH   64
#define TQ   64     // q rows per block
#define TK   64     // k/v rows per smem tile
#define NTHR 512

#define QS_STRIDE  68           // %32==4 -> conflict-free fragment rows
#define S_STRIDE   516          // %32==4
#define SMEM_FLOATS (TQ * QS_STRIDE + 2 * TK * QS_STRIDE + TQ * S_STRIDE)
#define SMEM_BYTES  (SMEM_FLOATS * sizeof(float))

__device__ __forceinline__ uint32_t f2tf(float x) {
    uint32_t r;
    asm("cvt.rna.tf32.f32 %0, %1;" : "=r"(r) : "f"(x));
    return r;
}
__device__ __forceinline__ uint32_t f2tf_bits(uint32_t xb) {
    uint32_t r;
    asm("cvt.rna.tf32.f32 %0, %1;" : "=r"(r) : "f"(__uint_as_float(xb)));
    return r;
}

__device__ __forceinline__ void mma_tf32(float d[4], const uint32_t a[4], const uint32_t b[2]) {
    asm volatile(
        "mma.sync.aligned.m16n8k8.row.col.f32.tf32.tf32.f32 "
        "{%0,%1,%2,%3}, {%4,%5,%6,%7}, {%8,%9}, {%0,%1,%2,%3};\n"
        : "+f"(d[0]), "+f"(d[1]), "+f"(d[2]), "+f"(d[3])
        : "r"(a[0]), "r"(a[1]), "r"(a[2]), "r"(a[3]), "r"(b[0]), "r"(b[1]));
}

// ldmatrix x4 on 32-bit data (fragment mapping verified on-chip in round 7)
__device__ __forceinline__ void ldsm_x4(uint32_t& r0, uint32_t& r1,
                                        uint32_t& r2, uint32_t& r3, uint32_t addr) {
    asm volatile("ldmatrix.sync.aligned.m8n8.x4.shared.b16 {%0,%1,%2,%3}, [%4];"
                 : "=r"(r0), "=r"(r1), "=r"(r2), "=r"(r3) : "r"(addr));
}

__device__ __forceinline__ void cp_async16(void* smem_ptr, const void* gptr) {
    uint32_t s = (uint32_t)__cvta_generic_to_shared(smem_ptr);
    asm volatile("cp.async.cg.shared.global [%0], [%1], 16;" :: "r"(s), "l"(gptr));
}
#define CP_COMMIT()  asm volatile("cp.async.commit_group;")
#define CP_WAIT0()   asm volatile("cp.async.wait_group 0;")

__device__ __forceinline__ void l2_prefetch(const void* gptr, uint32_t bytes) {
    asm volatile("cp.async.bulk.prefetch.L2.global [%0], %1;" :: "l"(gptr), "r"(bytes));
}

__global__ __launch_bounds__(NTHR, 1)
void attn_fused_kernel(const float* __restrict__ q,
                       const float* __restrict__ k,
                       const float* __restrict__ v,
                       const float* __restrict__ sel,
                       const int* __restrict__ mask,
                       float* __restrict__ ctx,
                       float* __restrict__ attn)
{
    extern __shared__ float sm[];
    float (*Qs)[QS_STRIDE]    = (float (*)[QS_STRIDE])sm;                         // [64][68]
    float (*KV)[TK][QS_STRIDE]= (float (*)[TK][QS_STRIDE])(sm + TQ * QS_STRIDE);  // [2][64][68]
    float (*S)[S_STRIDE]      = (float (*)[S_STRIDE])(sm + TQ * QS_STRIDE + 2 * TK * QS_STRIDE); // [64][516]

    const int bh  = blockIdx.y;
    const int qt  = blockIdx.x;
    const int tid = threadIdx.x;
    const int warp = tid >> 5, lane = tid & 31;
    const int wm = warp & 3;           // 4 warps along M: rows wm*16..+15
    const int wn = warp >> 2;          // 4 warps along N: 16 cols each
    const int g  = lane >> 2;          // fragment group 0..7
    const int t  = lane & 3;           // fragment thread-in-group 0..3

    const float* qg = q + ((size_t)bh * LSEQ + (size_t)qt * TQ) * DH;
    const float* kg = k + (size_t)bh * LSEQ * DH;
    const float* vg = v + (size_t)bh * LSEQ * DH;

    const size_t base = (size_t)bh * LSEQ * LSEQ + (size_t)qt * TQ * LSEQ;
    const float* selp = sel + base;
    const int* mp = mask + base;
    float* attnp = attn + base;

    // shared-address bases for ldmatrix
    const uint32_t smem_u32 = (uint32_t)__cvta_generic_to_shared(sm);
    const uint32_t kv_u32   = smem_u32 + TQ * QS_STRIDE * 4;
    const uint32_t s_u32    = smem_u32 + (TQ * QS_STRIDE + 2 * TK * QS_STRIDE) * 4;
    const uint32_t boff = (uint32_t)(((wn * 16 + (lane & 7)) * QS_STRIDE + 4 * (lane >> 3)) * 4);
    const uint32_t aoff = (uint32_t)(((wm * 16 + (lane & 15)) * S_STRIDE + 4 * (lane >> 4)) * 4);

    // ---- L2 prefetch of this CTA's sel + mask slices (contiguous 128 KB each).
    // DRAM streams them during GEMM1; softmax loads then hit L2.
    if (tid < 8) {
        l2_prefetch(selp + (size_t)tid * 4096, 16384);             // 8 x 16 KB = 128 KB
        l2_prefetch(mp   + (size_t)tid * 4096, 16384);             // 8 x 16 KB = 128 KB
    }

    // ---- prologue: async load Q tile + K tile 0 ----
    #pragma unroll
    for (int i = tid; i < TQ * DH / 4; i += NTHR) {
        int e = i * 4, r = e >> 6, c = e & 63;
        cp_async16(&Qs[r][c], qg + e);
        cp_async16(&KV[0][r][c], kg + e);
    }
    CP_COMMIT();
    CP_WAIT0();
    __syncthreads();

    // ---- hoist Q tf32 fragments, scale folded in (exact: 0.125 = 2^-3) ----
    uint32_t qa[DH / 8][4];
    #pragma unroll
    for (int ks = 0; ks < DH / 8; ++ks) {
        const int k0 = ks * 8;
        qa[ks][0] = f2tf(0.125f * Qs[wm * 16 + g    ][k0 + t    ]);
        qa[ks][1] = f2tf(0.125f * Qs[wm * 16 + g + 8][k0 + t    ]);
        qa[ks][2] = f2tf(0.125f * Qs[wm * 16 + g    ][k0 + t + 4]);
        qa[ks][3] = f2tf(0.125f * Qs[wm * 16 + g + 8][k0 + t + 4]);
    }

    // ---- phase 1: S = (Q*scale) @ K^T via tf32 mma, double-buffered K ----
    for (int kt = 0; kt < LSEQ / TK; ++kt) {
        if (kt > 0) {
            CP_WAIT0();
            __syncthreads();
        }
        if (kt + 1 < LSEQ / TK) {
            const float* kn = kg + (size_t)(kt + 1) * TK * DH;
            #pragma unroll
            for (int i = tid; i < TK * DH / 4; i += NTHR) {
                int e = i * 4, r = e >> 6, c = e & 63;
                cp_async16(&KV[(kt + 1) & 1][r][c], kn + e);
            }
            CP_COMMIT();
        }

        const uint32_t kbase = kv_u32 + (uint32_t)((kt & 1) * TK * QS_STRIDE * 4) + boff;
        float acc[2][4];
        #pragma unroll
        for (int nt = 0; nt < 2; ++nt)
            #pragma unroll
            for (int j = 0; j < 4; ++j) acc[nt][j] = 0.f;

        #pragma unroll
        for (int kb = 0; kb < 4; ++kb) {       // 16 k per block (2 k-steps)
            #pragma unroll
            for (int nt = 0; nt < 2; ++nt) {
                uint32_t b0, b1, b2, b3;
                ldsm_x4(b0, b1, b2, b3,
                        kbase + (uint32_t)((nt * 8 * QS_STRIDE + kb * 16) * 4));
                uint32_t blo[2] = {f2tf_bits(b0), f2tf_bits(b1)};
                uint32_t bhi[2] = {f2tf_bits(b2), f2tf_bits(b3)};
                mma_tf32(acc[nt], qa[2 * kb    ], blo);
                mma_tf32(acc[nt], qa[2 * kb + 1], bhi);
            }
        }

        #pragma unroll
        for (int nt = 0; nt < 2; ++nt) {
            const int n0 = kt * TK + wn * 16 + nt * 8 + 2 * t;
            S[wm * 16 + g    ][n0    ] = acc[nt][0];
            S[wm * 16 + g    ][n0 + 1] = acc[nt][1];
            S[wm * 16 + g + 8][n0    ] = acc[nt][2];
            S[wm * 16 + g + 8][n0 + 1] = acc[nt][3];
        }
    }

    // prefetch V tile 0 into buf 0 (overlaps softmax); buf0 last read at kt=6,
    // whose consumers all passed the kt=7 top barrier.
    #pragma unroll
    for (int i = tid; i < TK * DH / 4; i += NTHR) {
        int e = i * 4, r = e >> 6, c = e & 63;
        cp_async16(&KV[0][r][c], vg + e);
    }
    CP_COMMIT();
    __syncthreads();   // S complete for softmax

    // ---- phase 2: softmax, 4 rows per warp; attn fp32 out, S gets tf32 P ----
    {
        #pragma unroll
        for (int rr = 0; rr < 4; ++rr) {
            const int r = warp * 4 + rr;
            float vals[16];
            float lmax = -1e30f;
            #pragma unroll
            for (int i = 0; i < 4; ++i) {
                const int c = i * 128 + lane * 4;
                float4 sv = *(const float4*)&S[r][c];
                float4 se = *(const float4*)&selp[(size_t)r * LSEQ + c];
                int4  mv = *(const int4*)&mp[(size_t)r * LSEQ + c];
                float x0 = sv.x + se.x; if (mv.x == 0) x0 = -1e12f;
                float x1 = sv.y + se.y; if (mv.y == 0) x1 = -1e12f;
                float x2 = sv.z + se.z; if (mv.z == 0) x2 = -1e12f;
                float x3 = sv.w + se.w; if (mv.w == 0) x3 = -1e12f;
                vals[4 * i + 0] = x0; vals[4 * i + 1] = x1;
                vals[4 * i + 2] = x2; vals[4 * i + 3] = x3;
                lmax = fmaxf(lmax, fmaxf(fmaxf(x0, x1), fmaxf(x2, x3)));
            }
            #pragma unroll
            for (int o = 16; o > 0; o >>= 1)
                lmax = fmaxf(lmax, __shfl_xor_sync(0xffffffffu, lmax, o));
            float lsum = 0.f;
            #pragma unroll
            for (int i = 0; i < 16; ++i) {
                vals[i] = __expf(vals[i] - lmax);
                lsum += vals[i];
            }
            #pragma unroll
            for (int o = 16; o > 0; o >>= 1)
                lsum += __shfl_xor_sync(0xffffffffu, lsum, o);
            const float inv = 1.0f / lsum;
            #pragma unroll
            for (int i = 0; i < 4; ++i) {
                const int c = i * 128 + lane * 4;
                float4 a4;
                a4.x = vals[4 * i + 0] * inv;
                a4.y = vals[4 * i + 1] * inv;
                a4.z = vals[4 * i + 2] * inv;
                a4.w = vals[4 * i + 3] * inv;
                __stcs((float4*)&attnp[(size_t)r * LSEQ + c], a4);  // write-once, evict-first
                float4 p4;                                           // tf32-pre-rounded for PV
                p4.x = __uint_as_float(f2tf(a4.x));
                p4.y = __uint_as_float(f2tf(a4.y));
                p4.z = __uint_as_float(f2tf(a4.z));
                p4.w = __uint_as_float(f2tf(a4.w));
                *(float4*)&S[r][c] = p4;
            }
        }
    }
    __syncthreads();

    // ---- phase 3: ctx = P(S) @ V via tf32 mma, double-buffered V ----
    {
        float acc[2][4];
        #pragma unroll
        for (int nt = 0; nt < 2; ++nt)
            #pragma unroll
            for (int j = 0; j < 4; ++j) acc[nt][j] = 0.f;

        for (int vt = 0; vt < LSEQ / TK; ++vt) {
            CP_WAIT0();
            __syncthreads();
            if (vt + 1 < LSEQ / TK) {
                const float* vn = vg + (size_t)(vt + 1) * TK * DH;
                #pragma unroll
                for (int i = tid; i < TK * DH / 4; i += NTHR) {
                    int e = i * 4, r = e >> 6, c = e & 63;
                    cp_async16(&KV[(vt + 1) & 1][r][c], vn + e);
                }
                CP_COMMIT();
            }

            float (*Vs)[QS_STRIDE] = KV[vt & 1];
            #pragma unroll
            for (int ks = 0; ks < TK / 8; ++ks) {
                const int sk = vt * TK + ks * 8;   // S column (k index)
                const int vk = ks * 8;             // V smem row
                uint32_t a[4];                     // P pre-rounded: ldmatrix raw bits
                ldsm_x4(a[0], a[1], a[2], a[3], s_u32 + aoff + (uint32_t)(sk * 4));
                #pragma unroll
                for (int nt = 0; nt < 2; ++nt) {
                    const int n0 = wn * 16 + nt * 8;
                    uint32_t b[2];
                    b[0] = f2tf(Vs[vk + t    ][n0 + g]);
                    b[1] = f2tf(Vs[vk + t + 4][n0 + g]);
                    mma_tf32(acc[nt], a, b);
                }
            }
            __syncthreads();   // buf[vt&1] free for prefetch vt+2
        }

        float* cp = ctx + ((size_t)bh * LSEQ + (size_t)qt * TQ) * DH;
        #pragma unroll
        for (int nt = 0; nt < 2; ++nt) {
            const int n0 = wn * 16 + nt * 8 + 2 * t;
            __stcs((float2*)&cp[(size_t)(wm * 16 + g    ) * DH + n0],
                   make_float2(acc[nt][0], acc[nt][1]));
            __stcs((float2*)&cp[(size_t)(wm * 16 + g + 8) * DH + n0],
                   make_float2(acc[nt][2], acc[nt][3]));
        }
    }
}

extern "C" void kernel_launch(void* const* d_in, const int* in_sizes, int n_in,
                              void* d_out, int out_size)
{
    (void)in_sizes; (void)n_in; (void)out_size;
    const float* q = (const float*)d_in[0];
    const float* k = (const float*)d_in[1];
    const float* v = (const float*)d_in[2];
    const float* sel = (const float*)d_in[3];
    const int* mask = (const int*)d_in[4];

    float* ctx  = (float*)d_out;                          // [128,512,64]
    float* attn = ctx + (size_t)BH * LSEQ * DH;           // [128,512,512]

    cudaFuncSetAttribute(attn_fused_kernel,
                         cudaFuncAttributeMaxDynamicSharedMemorySize, (int)SMEM_BYTES);

    dim3 grid(LSEQ / TQ, BH);   // (8, 128) = 1024 blocks
    attn_fused_kernel<<<grid, NTHR, SMEM_BYTES>>>(q, k, v, sel, mask, ctx, attn);
}

// round 11
// speedup vs baseline: 1.0313x; 1.0313x over previous
#include <cuda_runtime.h>
#include <cstdint>

// Problem constants (fixed by the reference: B=8, H=16, L=512, D=64)
#define BH   128
#define LSEQ 512
#define DH   64
#define TQ   64     // q rows per block
#define TK   64     // k/v rows per smem tile
#define NTHR 512

#define QS_STRIDE  68           // %32==4 -> conflict-free fragment rows
#define S_STRIDE   516          // %32==4
#define SMEM_FLOATS (TQ * QS_STRIDE + 2 * TK * QS_STRIDE + TQ * S_STRIDE + 4 * TQ)
#define SMEM_BYTES  (SMEM_FLOATS * sizeof(float))

__device__ __forceinline__ uint32_t f2tf(float x) {
    uint32_t r;
    asm("cvt.rna.tf32.f32 %0, %1;" : "=r"(r) : "f"(x));
    return r;
}
__device__ __forceinline__ uint32_t f2tf_bits(uint32_t xb) {
    uint32_t r;
    asm("cvt.rna.tf32.f32 %0, %1;" : "=r"(r) : "f"(__uint_as_float(xb)));
    return r;
}

__device__ __forceinline__ void mma_tf32(float d[4], const uint32_t a[4], const uint32_t b[2]) {
    asm volatile(
        "mma.sync.aligned.m16n8k8.row.col.f32.tf32.tf32.f32 "
        "{%0,%1,%2,%3}, {%4,%5,%6,%7}, {%8,%9}, {%0,%1,%2,%3};\n"
        : "+f"(d[0]), "+f"(d[1]), "+f"(d[2]), "+f"(d[3])
        : "r"(a[0]), "r"(a[1]), "r"(a[2]), "r"(a[3]), "r"(b[0]), "r"(b[1]));
}

// ldmatrix x4 on 32-bit data (fragment mapping verified on-chip in round 7)
__device__ __forceinline__ void ldsm_x4(uint32_t& r0, uint32_t& r1,
                                        uint32_t& r2, uint32_t& r3, uint32_t addr) {
    asm volatile("ldmatrix.sync.aligned.m8n8.x4.shared.b16 {%0,%1,%2,%3}, [%4];"
                 : "=r"(r0), "=r"(r1), "=r"(r2), "=r"(r3) : "r"(addr));
}

__device__ __forceinline__ void cp_async16(void* smem_ptr, const void* gptr) {
    uint32_t s = (uint32_t)__cvta_generic_to_shared(smem_ptr);
    asm volatile("cp.async.cg.shared.global [%0], [%1], 16;" :: "r"(s), "l"(gptr));
}
#define CP_COMMIT()  asm volatile("cp.async.commit_group;")
#define CP_WAIT0()   asm volatile("cp.async.wait_group 0;")

__global__ __launch_bounds__(NTHR, 1)
void attn_fused_kernel(const float* __restrict__ q,
                       const float* __restrict__ k,
                       const float* __restrict__ v,
                       const float* __restrict__ sel,
                       const int* __restrict__ mask,
                       float* __restrict__ ctx,
                       float* __restrict__ attn)
{
    extern __shared__ float sm[];
    float (*Qs)[QS_STRIDE]    = (float (*)[QS_STRIDE])sm;                         // [64][68]
    float (*KV)[TK][QS_STRIDE]= (float (*)[TK][QS_STRIDE])(sm + TQ * QS_STRIDE);  // [2][64][68]
    float (*S)[S_STRIDE]      = (float (*)[S_STRIDE])(sm + TQ * QS_STRIDE + 2 * TK * QS_STRIDE); // [64][516]
    float (*Rmax)[TQ]         = (float (*)[TQ])(sm + TQ * QS_STRIDE + 2 * TK * QS_STRIDE + TQ * S_STRIDE); // [4][64]

    const int bh  = blockIdx.y;
    const int qt  = blockIdx.x;
    const int tid = threadIdx.x;
    const int warp = tid >> 5, lane = tid & 31;
    const int wm = warp & 3;           // 4 warps along M: rows wm*16..+15
    const int wn = warp >> 2;          // 4 warps along N: 16 cols each
    const int g  = lane >> 2;          // fragment group 0..7
    const int t  = lane & 3;           // fragment thread-in-group 0..3

    const float* qg = q + ((size_t)bh * LSEQ + (size_t)qt * TQ) * DH;
    const float* kg = k + (size_t)bh * LSEQ * DH;
    const float* vg = v + (size_t)bh * LSEQ * DH;

    const size_t base = (size_t)bh * LSEQ * LSEQ + (size_t)qt * TQ * LSEQ;
    const float* selp = sel + base;
    const int* mp = mask + base;
    float* attnp = attn + base;

    // shared-address bases for ldmatrix
    const uint32_t smem_u32 = (uint32_t)__cvta_generic_to_shared(sm);
    const uint32_t kv_u32   = smem_u32 + TQ * QS_STRIDE * 4;
    const uint32_t s_u32    = smem_u32 + (TQ * QS_STRIDE + 2 * TK * QS_STRIDE) * 4;
    const uint32_t boff = (uint32_t)(((wn * 16 + (lane & 7)) * QS_STRIDE + 4 * (lane >> 3)) * 4);
    const uint32_t aoff = (uint32_t)(((wm * 16 + (lane & 15)) * S_STRIDE + 4 * (lane >> 4)) * 4);

    // staging coords: thread -> (row, col4) within a 64x64 sel/mask block
    const int sr0 = tid >> 4;               // rows 0..31  (j=0)
    const int sc  = (tid & 15) * 4;         // col group

    // ---- prologue: async load Q tile + K tile 0 ----
    #pragma unroll
    for (int i = tid; i < TQ * DH / 4; i += NTHR) {
        int e = i * 4, r = e >> 6, c = e & 63;
        cp_async16(&Qs[r][c], qg + e);
        cp_async16(&KV[0][r][c], kg + e);
    }
    CP_COMMIT();
    CP_WAIT0();
    __syncthreads();

    // ---- hoist Q tf32 fragments, scale folded in (exact: 0.125 = 2^-3) ----
    uint32_t qa[DH / 8][4];
    #pragma unroll
    for (int ks = 0; ks < DH / 8; ++ks) {
        const int k0 = ks * 8;
        qa[ks][0] = f2tf(0.125f * Qs[wm * 16 + g    ][k0 + t    ]);
        qa[ks][1] = f2tf(0.125f * Qs[wm * 16 + g + 8][k0 + t    ]);
        qa[ks][2] = f2tf(0.125f * Qs[wm * 16 + g    ][k0 + t + 4]);
        qa[ks][3] = f2tf(0.125f * Qs[wm * 16 + g + 8][k0 + t + 4]);
    }

    const int r0 = wm * 16 + g;        // this thread's two S rows
    const int r1 = r0 + 8;
    float rm0 = -1e30f, rm1 = -1e30f;  // running row maxima

    // ---- phase 1: S = (Q*scale)@K^T + sel, masked; sel/mask staged via S ----
    for (int kt = 0; kt < LSEQ / TK; ++kt) {
        if (kt > 0) {
            CP_WAIT0();
            __syncthreads();
        }
        if (kt + 1 < LSEQ / TK) {
            const float* kn = kg + (size_t)(kt + 1) * TK * DH;
            #pragma unroll
            for (int i = tid; i < TK * DH / 4; i += NTHR) {
                int e = i * 4, r = e >> 6, c = e & 63;
                cp_async16(&KV[(kt + 1) & 1][r][c], kn + e);
            }
            CP_COMMIT();
        }

        // issue coalesced staging loads for this tile's sel/mask block (regs)
        float4 se0 = *(const float4*)&selp[(size_t)sr0 * LSEQ + kt * TK + sc];
        int4   mv0 = *(const int4*)  &mp  [(size_t)sr0 * LSEQ + kt * TK + sc];
        float4 se1 = *(const float4*)&selp[(size_t)(sr0 + 32) * LSEQ + kt * TK + sc];
        int4   mv1 = *(const int4*)  &mp  [(size_t)(sr0 + 32) * LSEQ + kt * TK + sc];

        // mma compute (independent of staging loads -> covers their latency)
        const uint32_t kbase = kv_u32 + (uint32_t)((kt & 1) * TK * QS_STRIDE * 4) + boff;
        float acc[2][4];
        #pragma unroll
        for (int nt = 0; nt < 2; ++nt)
            #pragma unroll
            for (int j = 0; j < 4; ++j) acc[nt][j] = 0.f;

        #pragma unroll
        for (int kb = 0; kb < 4; ++kb) {
            #pragma unroll
            for (int nt = 0; nt < 2; ++nt) {
                uint32_t b0, b1, b2, b3;
                ldsm_x4(b0, b1, b2, b3,
                        kbase + (uint32_t)((nt * 8 * QS_STRIDE + kb * 16) * 4));
                uint32_t blo[2] = {f2tf_bits(b0), f2tf_bits(b1)};
                uint32_t bhi[2] = {f2tf_bits(b2), f2tf_bits(b3)};
                mma_tf32(acc[nt], qa[2 * kb    ], blo);
                mma_tf32(acc[nt], qa[2 * kb + 1], bhi);
            }
        }

        // store staged msel = mask ? sel : -2e12 into S (region this tile owns)
        {
            float4 ms;
            ms.x = mv0.x ? se0.x : -2e12f;
            ms.y = mv0.y ? se0.y : -2e12f;
            ms.z = mv0.z ? se0.z : -2e12f;
            ms.w = mv0.w ? se0.w : -2e12f;
            *(float4*)&S[sr0][kt * TK + sc] = ms;
            ms.x = mv1.x ? se1.x : -2e12f;
            ms.y = mv1.y ? se1.y : -2e12f;
            ms.z = mv1.z ? se1.z : -2e12f;
            ms.w = mv1.w ? se1.w : -2e12f;
            *(float4*)&S[sr0 + 32][kt * TK + sc] = ms;
        }
        __syncthreads();   // staged msel visible to fragment owners

        // epilogue: x = acc + msel, clamp masked to exactly -1e12, track max
        #pragma unroll
        for (int nt = 0; nt < 2; ++nt) {
            const int n0 = kt * TK + wn * 16 + nt * 8 + 2 * t;
            float2 m0 = *(float2*)&S[r0][n0];
            float2 m1 = *(float2*)&S[r1][n0];
            float x00 = acc[nt][0] + m0.x; if (x00 < -1e11f) x00 = -1e12f;
            float x01 = acc[nt][1] + m0.y; if (x01 < -1e11f) x01 = -1e12f;
            float x10 = acc[nt][2] + m1.x; if (x10 < -1e11f) x10 = -1e12f;
            float x11 = acc[nt][3] + m1.y; if (x11 < -1e11f) x11 = -1e12f;
            *(float2*)&S[r0][n0] = make_float2(x00, x01);
            *(float2*)&S[r1][n0] = make_float2(x10, x11);
            rm0 = fmaxf(rm0, fmaxf(x00, x01));
            rm1 = fmaxf(rm1, fmaxf(x10, x11));
        }
    }

    // reduce row max across the 4 lanes of each quad (lanes t=0..3 share rows)
    rm0 = fmaxf(rm0, __shfl_xor_sync(0xffffffffu, rm0, 1));
    rm0 = fmaxf(rm0, __shfl_xor_sync(0xffffffffu, rm0, 2));
    rm1 = fmaxf(rm1, __shfl_xor_sync(0xffffffffu, rm1, 1));
    rm1 = fmaxf(rm1, __shfl_xor_sync(0xffffffffu, rm1, 2));
    if (t == 0) {
        Rmax[wn][r0] = rm0;
        Rmax[wn][r1] = rm1;
    }

    // prefetch V tile 0 into buf 0 (overlaps softmax)
    #pragma unroll
    for (int i = tid; i < TK * DH / 4; i += NTHR) {
        int e = i * 4, r = e >> 6, c = e & 63;
        cp_async16(&KV[0][r][c], vg + e);
    }
    CP_COMMIT();
    __syncthreads();   // S (masked+biased) + Rmax complete

    // ---- phase 2: softmax (no global reads); attn fp32 out, S gets tf32 P ----
    #pragma unroll
    for (int rr = 0; rr < 4; ++rr) {
        const int r = warp * 4 + rr;
        const float lmax = fmaxf(fmaxf(Rmax[0][r], Rmax[1][r]),
                                 fmaxf(Rmax[2][r], Rmax[3][r]));
        float vals[16];
        float lsum = 0.f;
        #pragma unroll
        for (int i = 0; i < 4; ++i) {
            const int c = i * 128 + lane * 4;
            float4 sv = *(const float4*)&S[r][c];
            vals[4 * i + 0] = __expf(sv.x - lmax);
            vals[4 * i + 1] = __expf(sv.y - lmax);
            vals[4 * i + 2] = __expf(sv.z - lmax);
            vals[4 * i + 3] = __expf(sv.w - lmax);
            lsum += (vals[4*i+0] + vals[4*i+1]) + (vals[4*i+2] + vals[4*i+3]);
        }
        #pragma unroll
        for (int o = 16; o > 0; o >>= 1)
            lsum += __shfl_xor_sync(0xffffffffu, lsum, o);
        const float inv = 1.0f / lsum;
        #pragma unroll
        for (int i = 0; i < 4; ++i) {
            const int c = i * 128 + lane * 4;
            float4 a4;
            a4.x = vals[4 * i + 0] * inv;
            a4.y = vals[4 * i + 1] * inv;
            a4.z = vals[4 * i + 2] * inv;
            a4.w = vals[4 * i + 3] * inv;
            *(float4*)&attnp[(size_t)r * LSEQ + c] = a4;   // plain stores (lesson R6/R7/R9)
            float4 p4;                                      // tf32-pre-rounded for PV
            p4.x = __uint_as_float(f2tf(a4.x));
            p4.y = __uint_as_float(f2tf(a4.y));
            p4.z = __uint_as_float(f2tf(a4.z));
            p4.w = __uint_as_float(f2tf(a4.w));
            *(float4*)&S[r][c] = p4;
        }
    }
    __syncthreads();

    // ---- phase 3: ctx = P(S) @ V via tf32 mma, double-buffered V ----
    {
        float acc[2][4];
        #pragma unroll
        for (int nt = 0; nt < 2; ++nt)
            #pragma unroll
            for (int j = 0; j < 4; ++j) acc[nt][j] = 0.f;

        for (int vt = 0; vt < LSEQ / TK; ++vt) {
            CP_WAIT0();
            __syncthreads();
            if (vt + 1 < LSEQ / TK) {
                const float* vn = vg + (size_t)(vt + 1) * TK * DH;
                #pragma unroll
                for (int i = tid; i < TK * DH / 4; i += NTHR) {
                    int e = i * 4, r = e >> 6, c = e & 63;
                    cp_async16(&KV[(vt + 1) & 1][r][c], vn + e);
                }
                CP_COMMIT();
            }

            float (*Vs)[QS_STRIDE] = KV[vt & 1];
            #pragma unroll
            for (int ks = 0; ks < TK / 8; ++ks) {
                const int sk = vt * TK + ks * 8;   // S column (k index)
                const int vk = ks * 8;             // V smem row
                uint32_t a[4];                     // P pre-rounded: ldmatrix raw bits
                ldsm_x4(a[0], a[1], a[2], a[3], s_u32 + aoff + (uint32_t)(sk * 4));
                #pragma unroll
                for (int nt = 0; nt < 2; ++nt) {
                    const int n0 = wn * 16 + nt * 8;
                    uint32_t b[2];
                    b[0] = f2tf(Vs[vk + t    ][n0 + g]);
                    b[1] = f2tf(Vs[vk + t + 4][n0 + g]);
                    mma_tf32(acc[nt], a, b);
                }
            }
            __syncthreads();   // buf[vt&1] free for prefetch vt+2
        }

        float* cp = ctx + ((size_t)bh * LSEQ + (size_t)qt * TQ) * DH;
        #pragma unroll
        for (int nt = 0; nt < 2; ++nt) {
            const int n0 = wn * 16 + nt * 8 + 2 * t;
            float2 lo = make_float2(acc[nt][0], acc[nt][1]);
            float2 hi = make_float2(acc[nt][2], acc[nt][3]);
            *(float2*)&cp[(size_t)r0 * DH + n0] = lo;
            *(float2*)&cp[(size_t)r1 * DH + n0] = hi;
        }
    }
}

extern "C" void kernel_launch(void* const* d_in, const int* in_sizes, int n_in,
                              void* d_out, int out_size)
{
    (void)in_sizes; (void)n_in; (void)out_size;
    const float* q = (const float*)d_in[0];
    const float* k = (const float*)d_in[1];
    const float* v = (const float*)d_in[2];
    const float* sel = (const float*)d_in[3];
    const int* mask = (const int*)d_in[4];

    float* ctx  = (float*)d_out;                          // [128,512,64]
    float* attn = ctx + (size_t)BH * LSEQ * DH;           // [128,512,512]

    cudaFuncSetAttribute(attn_fused_kernel,
                         cudaFuncAttributeMaxDynamicSharedMemorySize, (int)SMEM_BYTES);

    dim3 grid(LSEQ / TQ, BH);   // (8, 128) = 1024 blocks
    attn_fused_kernel<<<grid, NTHR, SMEM_BYTES>>>(q, k, v, sel, mask, ctx, attn);
}

// round 12
// speedup vs baseline: 1.1465x; 1.1117x over previous
#include <cuda_runtime.h>
#include <cstdint>

// Problem constants (fixed by the reference: B=8, H=16, L=512, D=64)
#define BH   128
#define LSEQ 512
#define DH   64
#define TQ   64     // q rows per block
#define TK   64     // k/v tile cols/rows
#define NTHR 512

#define QS_STRIDE  68           // %32==4 -> conflict-free fragment rows
#define S_STRIDE   516          // %32==4
#define SMEM_FLOATS (TQ * QS_STRIDE + 2 * TK * QS_STRIDE + TQ * S_STRIDE + TQ)
#define SMEM_BYTES  (SMEM_FLOATS * sizeof(float))

__device__ __forceinline__ uint32_t f2tf(float x) {
    uint32_t r;
    asm("cvt.rna.tf32.f32 %0, %1;" : "=r"(r) : "f"(x));
    return r;
}
__device__ __forceinline__ uint32_t f2tf_bits(uint32_t xb) {
    uint32_t r;
    asm("cvt.rna.tf32.f32 %0, %1;" : "=r"(r) : "f"(__uint_as_float(xb)));
    return r;
}

__device__ __forceinline__ void mma_tf32(float d[4], const uint32_t a[4], const uint32_t b[2]) {
    asm volatile(
        "mma.sync.aligned.m16n8k8.row.col.f32.tf32.tf32.f32 "
        "{%0,%1,%2,%3}, {%4,%5,%6,%7}, {%8,%9}, {%0,%1,%2,%3};\n"
        : "+f"(d[0]), "+f"(d[1]), "+f"(d[2]), "+f"(d[3])
        : "r"(a[0]), "r"(a[1]), "r"(a[2]), "r"(a[3]), "r"(b[0]), "r"(b[1]));
}

// ldmatrix x4 on 32-bit data (fragment mapping verified on-chip in round 7)
__device__ __forceinline__ void ldsm_x4(uint32_t& r0, uint32_t& r1,
                                        uint32_t& r2, uint32_t& r3, uint32_t addr) {
    asm volatile("ldmatrix.sync.aligned.m8n8.x4.shared.b16 {%0,%1,%2,%3}, [%4];"
                 : "=r"(r0), "=r"(r1), "=r"(r2), "=r"(r3) : "r"(addr));
}

__device__ __forceinline__ void cp_async16(void* smem_ptr, const void* gptr) {
    uint32_t s = (uint32_t)__cvta_generic_to_shared(smem_ptr);
    asm volatile("cp.async.cg.shared.global [%0], [%1], 16;" :: "r"(s), "l"(gptr));
}
#define CP_COMMIT()  asm volatile("cp.async.commit_group;")
#define CP_WAIT0()   asm volatile("cp.async.wait_group 0;")

// named barriers: producer arrives, consumer syncs; count = all participants
#define BAR_ARRIVE(id)  asm volatile("bar.arrive %0, 512;" :: "r"(id))
#define BAR_SYNC(id)    asm volatile("bar.sync %0, 512;" :: "r"(id) : "memory")
#define BAR_A_GROUP()   asm volatile("bar.sync 9, 256;" ::: "memory")
#define MEMBAR_CTA()    asm volatile("membar.cta;" ::: "memory")

__global__ __launch_bounds__(NTHR, 1)
void attn_fused_kernel(const float* __restrict__ q,
                       const float* __restrict__ k,
                       const float* __restrict__ v,
                       const float* __restrict__ sel,
                       const int* __restrict__ mask,
                       float* __restrict__ ctx,
                       float* __restrict__ attn)
{
    extern __shared__ float sm[];
    float (*Qs)[QS_STRIDE]    = (float (*)[QS_STRIDE])sm;                         // [64][68]
    float (*KV)[TK][QS_STRIDE]= (float (*)[TK][QS_STRIDE])(sm + TQ * QS_STRIDE);  // [2][64][68]
    float (*S)[S_STRIDE]      = (float (*)[S_STRIDE])(sm + TQ * QS_STRIDE + 2 * TK * QS_STRIDE); // [64][516]
    float* Rmax               = sm + TQ * QS_STRIDE + 2 * TK * QS_STRIDE + TQ * S_STRIDE;        // [64]

    const int bh  = blockIdx.y;
    const int qt  = blockIdx.x;
    const int tid = threadIdx.x;
    const int warp = tid >> 5, lane = tid & 31;
    const int g  = lane >> 2;          // fragment group 0..7
    const int t  = lane & 3;           // fragment thread-in-group 0..3

    const float* qg = q + ((size_t)bh * LSEQ + (size_t)qt * TQ) * DH;
    const float* kg = k + (size_t)bh * LSEQ * DH;
    const float* vg = v + (size_t)bh * LSEQ * DH;

    const size_t base = (size_t)bh * LSEQ * LSEQ + (size_t)qt * TQ * LSEQ;
    const float* selp = sel + base;
    const int* mp = mask + base;
    float* attnp = attn + base;

    // shared-address bases for ldmatrix
    const uint32_t smem_u32 = (uint32_t)__cvta_generic_to_shared(sm);
    const uint32_t kv_u32   = smem_u32 + TQ * QS_STRIDE * 4;
    const uint32_t s_u32    = smem_u32 + (TQ * QS_STRIDE + 2 * TK * QS_STRIDE) * 4;

    // ---- prologue: async load Q tile + K tile 0 (all threads) ----
    #pragma unroll
    for (int i = tid; i < TQ * DH / 4; i += NTHR) {
        int e = i * 4, r = e >> 6, c = e & 63;
        cp_async16(&Qs[r][c], qg + e);
        cp_async16(&KV[0][r][c], kg + e);
    }
    CP_COMMIT();
    CP_WAIT0();
    __syncthreads();

    // =====================================================================
    // phase 1 (warp-specialized): A = warps 0..7 compute raw S = (Q*s)@K^T;
    //                             B = warps 8..15 stream sel/mask, finish S.
    // =====================================================================
    if (warp < 8) {
        // ---- group A: GEMM producer ----
        const int wm = warp & 3;           // rows wm*16..+15
        const int wn = warp >> 2;          // cols wn*32..+31 (4 nt sub-tiles)
        const int atid = tid;              // 0..255
        const uint32_t boff = (uint32_t)(((wn * 32 + (lane & 7)) * QS_STRIDE + 4 * (lane >> 3)) * 4);

        uint32_t qa[DH / 8][4];
        #pragma unroll
        for (int ks = 0; ks < DH / 8; ++ks) {
            const int k0 = ks * 8;
            qa[ks][0] = f2tf(0.125f * Qs[wm * 16 + g    ][k0 + t    ]);
            qa[ks][1] = f2tf(0.125f * Qs[wm * 16 + g + 8][k0 + t    ]);
            qa[ks][2] = f2tf(0.125f * Qs[wm * 16 + g    ][k0 + t + 4]);
            qa[ks][3] = f2tf(0.125f * Qs[wm * 16 + g + 8][k0 + t + 4]);
        }

        for (int kt = 0; kt < LSEQ / TK; ++kt) {
            if (kt > 0) {
                CP_WAIT0();
                BAR_A_GROUP();
            }
            if (kt + 1 < LSEQ / TK) {
                const float* kn = kg + (size_t)(kt + 1) * TK * DH;
                #pragma unroll
                for (int i = atid; i < TK * DH / 4; i += 256) {
                    int e = i * 4, r = e >> 6, c = e & 63;
                    cp_async16(&KV[(kt + 1) & 1][r][c], kn + e);
                }
                CP_COMMIT();
            }

            const uint32_t kbase = kv_u32 + (uint32_t)((kt & 1) * TK * QS_STRIDE * 4) + boff;
            float acc[4][4];
            #pragma unroll
            for (int nt = 0; nt < 4; ++nt)
                #pragma unroll
                for (int j = 0; j < 4; ++j) acc[nt][j] = 0.f;

            #pragma unroll
            for (int kb = 0; kb < 4; ++kb) {
                #pragma unroll
                for (int nt = 0; nt < 4; ++nt) {
                    uint32_t b0, b1, b2, b3;
                    ldsm_x4(b0, b1, b2, b3,
                            kbase + (uint32_t)((nt * 8 * QS_STRIDE + kb * 16) * 4));
                    uint32_t blo[2] = {f2tf_bits(b0), f2tf_bits(b1)};
                    uint32_t bhi[2] = {f2tf_bits(b2), f2tf_bits(b3)};
                    mma_tf32(acc[nt], qa[2 * kb    ], blo);
                    mma_tf32(acc[nt], qa[2 * kb + 1], bhi);
                }
            }

            #pragma unroll
            for (int nt = 0; nt < 4; ++nt) {
                const int n0 = kt * TK + wn * 32 + nt * 8 + 2 * t;
                *(float2*)&S[wm * 16 + g    ][n0] = make_float2(acc[nt][0], acc[nt][1]);
                *(float2*)&S[wm * 16 + g + 8][n0] = make_float2(acc[nt][2], acc[nt][3]);
            }
            MEMBAR_CTA();           // make STS visible before signaling B
            BAR_ARRIVE(1 + kt);     // tile kt ready for group B
        }

        // prefetch V tile 0 into buf 0 (overlaps B's tail + softmax)
        #pragma unroll
        for (int i = atid; i < TK * DH / 4; i += 256) {
            int e = i * 4, r = e >> 6, c = e & 63;
            cp_async16(&KV[0][r][c], vg + e);
        }
        CP_COMMIT();
    } else {
        // ---- group B: sel/mask streamer + masking consumer ----
        const int bw = warp - 8;           // 0..7 -> rows bw*8..+7
        float m[8];
        #pragma unroll
        for (int j = 0; j < 8; ++j) m[j] = -1e30f;

        for (int kt = 0; kt < LSEQ / TK; ++kt) {
            BAR_SYNC(1 + kt);              // wait for A's tile kt scores
            const int c = kt * TK + lane * 2;
            #pragma unroll
            for (int j = 0; j < 8; ++j) {
                const int r = bw * 8 + j;
                float2 sv = *(float2*)&S[r][c];
                float2 se = *(const float2*)&selp[(size_t)r * LSEQ + c];
                int2   mv = *(const int2*)  &mp  [(size_t)r * LSEQ + c];
                float x0 = mv.x ? sv.x + se.x : -1e12f;
                float x1 = mv.y ? sv.y + se.y : -1e12f;
                *(float2*)&S[r][c] = make_float2(x0, x1);
                m[j] = fmaxf(m[j], fmaxf(x0, x1));
            }
        }
        // warp-reduce row maxima, write Rmax
        #pragma unroll
        for (int j = 0; j < 8; ++j) {
            float mm = m[j];
            #pragma unroll
            for (int o = 16; o > 0; o >>= 1)
                mm = fmaxf(mm, __shfl_xor_sync(0xffffffffu, mm, o));
            if (lane == 0) Rmax[bw * 8 + j] = mm;
        }
    }
    __syncthreads();   // S (masked+biased) + Rmax complete; V tile0 in flight

    // ---- phase 2: softmax (no global reads); attn fp32 out, S gets tf32 P ----
    #pragma unroll
    for (int rr = 0; rr < 4; ++rr) {
        const int r = warp * 4 + rr;
        const float lmax = Rmax[r];
        float vals[16];
        float lsum = 0.f;
        #pragma unroll
        for (int i = 0; i < 4; ++i) {
            const int c = i * 128 + lane * 4;
            float4 sv = *(const float4*)&S[r][c];
            vals[4 * i + 0] = __expf(sv.x - lmax);
            vals[4 * i + 1] = __expf(sv.y - lmax);
            vals[4 * i + 2] = __expf(sv.z - lmax);
            vals[4 * i + 3] = __expf(sv.w - lmax);
            lsum += (vals[4*i+0] + vals[4*i+1]) + (vals[4*i+2] + vals[4*i+3]);
        }
        #pragma unroll
        for (int o = 16; o > 0; o >>= 1)
            lsum += __shfl_xor_sync(0xffffffffu, lsum, o);
        const float inv = 1.0f / lsum;
        #pragma unroll
        for (int i = 0; i < 4; ++i) {
            const int c = i * 128 + lane * 4;
            float4 a4;
            a4.x = vals[4 * i + 0] * inv;
            a4.y = vals[4 * i + 1] * inv;
            a4.z = vals[4 * i + 2] * inv;
            a4.w = vals[4 * i + 3] * inv;
            *(float4*)&attnp[(size_t)r * LSEQ + c] = a4;   // plain stores (R6/R9 lesson)
            float4 p4;                                      // tf32-pre-rounded for PV
            p4.x = __uint_as_float(f2tf(a4.x));
            p4.y = __uint_as_float(f2tf(a4.y));
            p4.z = __uint_as_float(f2tf(a4.z));
            p4.w = __uint_as_float(f2tf(a4.w));
            *(float4*)&S[r][c] = p4;
        }
    }
    __syncthreads();

    // ---- phase 3: ctx = P(S) @ V via tf32 mma, double-buffered V (16 warps) ----
    {
        const int wm = warp & 3;
        const int wn = warp >> 2;
        const uint32_t aoff = (uint32_t)(((wm * 16 + (lane & 15)) * S_STRIDE + 4 * (lane >> 4)) * 4);

        float acc[2][4];
        #pragma unroll
        for (int nt = 0; nt < 2; ++nt)
            #pragma unroll
            for (int j = 0; j < 4; ++j) acc[nt][j] = 0.f;

        for (int vt = 0; vt < LSEQ / TK; ++vt) {
            CP_WAIT0();
            __syncthreads();
            if (vt + 1 < LSEQ / TK) {
                const float* vn = vg + (size_t)(vt + 1) * TK * DH;
                #pragma unroll
                for (int i = tid; i < TK * DH / 4; i += NTHR) {
                    int e = i * 4, r = e >> 6, c = e & 63;
                    cp_async16(&KV[(vt + 1) & 1][r][c], vn + e);
                }
                CP_COMMIT();
            }

            float (*Vs)[QS_STRIDE] = KV[vt & 1];
            #pragma unroll
            for (int ks = 0; ks < TK / 8; ++ks) {
                const int sk = vt * TK + ks * 8;   // S column (k index)
                const int vk = ks * 8;             // V smem row
                uint32_t a[4];                     // P pre-rounded: ldmatrix raw bits
                ldsm_x4(a[0], a[1], a[2], a[3], s_u32 + aoff + (uint32_t)(sk * 4));
                #pragma unroll
                for (int nt = 0; nt < 2; ++nt) {
                    const int n0 = wn * 16 + nt * 8;
                    uint32_t b[2];
                    b[0] = f2tf(Vs[vk + t    ][n0 + g]);
                    b[1] = f2tf(Vs[vk + t + 4][n0 + g]);
                    mma_tf32(acc[nt], a, b);
                }
            }
            __syncthreads();   // buf[vt&1] free for prefetch vt+2
        }

        float* cp = ctx + ((size_t)bh * LSEQ + (size_t)qt * TQ) * DH;
        #pragma unroll
        for (int nt = 0; nt < 2; ++nt) {
            const int n0 = wn * 16 + nt * 8 + 2 * t;
            *(float2*)&cp[(size_t)(wm * 16 + g    ) * DH + n0] = make_float2(acc[nt][0], acc[nt][1]);
            *(float2*)&cp[(size_t)(wm * 16 + g + 8) * DH + n0] = make_float2(acc[nt][2], acc[nt][3]);
        }
    }
}

extern "C" void kernel_launch(void* const* d_in, const int* in_sizes, int n_in,
                              void* d_out, int out_size)
{
    (void)in_sizes; (void)n_in; (void)out_size;
    const float* q = (const float*)d_in[0];
    const float* k = (const float*)d_in[1];
    const float* v = (const float*)d_in[2];
    const float* sel = (const float*)d_in[3];
    const int* mask = (const int*)d_in[4];

    float* ctx  = (float*)d_out;                          // [128,512,64]
    float* attn = ctx + (size_t)BH * LSEQ * DH;           // [128,512,512]

    cudaFuncSetAttribute(attn_fused_kernel,
                         cudaFuncAttributeMaxDynamicSharedMemorySize, (int)SMEM_BYTES);

    dim3 grid(LSEQ / TQ, BH);   // (8, 128) = 1024 blocks
    attn_fused_kernel<<<grid, NTHR, SMEM_BYTES>>>(q, k, v, sel, mask, ctx, attn);
}

// round 13
// speedup vs baseline: 1.1494x; 1.0025x over previous
#include <cuda_runtime.h>
#include <cstdint>

// Problem constants (fixed by the reference: B=8, H=16, L=512, D=64)
#define BH   128
#define LSEQ 512
#define DH   64
#define TQ   64     // q rows per block
#define TK   64     // k/v tile cols/rows
#define NTHR 512

#define QS_STRIDE  68           // %32==4 -> conflict-free fragment rows
#define S_STRIDE   516          // %32==4
#define SMEM_FLOATS (TQ * QS_STRIDE + 2 * TK * QS_STRIDE + TQ * S_STRIDE + 2 * TQ)
#define SMEM_BYTES  (SMEM_FLOATS * sizeof(float))

__device__ __forceinline__ uint32_t f2tf(float x) {
    uint32_t r;
    asm("cvt.rna.tf32.f32 %0, %1;" : "=r"(r) : "f"(x));
    return r;
}
__device__ __forceinline__ uint32_t f2tf_bits(uint32_t xb) {
    uint32_t r;
    asm("cvt.rna.tf32.f32 %0, %1;" : "=r"(r) : "f"(__uint_as_float(xb)));
    return r;
}

__device__ __forceinline__ void mma_tf32(float d[4], const uint32_t a[4], const uint32_t b[2]) {
    asm volatile(
        "mma.sync.aligned.m16n8k8.row.col.f32.tf32.tf32.f32 "
        "{%0,%1,%2,%3}, {%4,%5,%6,%7}, {%8,%9}, {%0,%1,%2,%3};\n"
        : "+f"(d[0]), "+f"(d[1]), "+f"(d[2]), "+f"(d[3])
        : "r"(a[0]), "r"(a[1]), "r"(a[2]), "r"(a[3]), "r"(b[0]), "r"(b[1]));
}

// ldmatrix x4 on 32-bit data (fragment mapping verified on-chip in round 7)
__device__ __forceinline__ void ldsm_x4(uint32_t& r0, uint32_t& r1,
                                        uint32_t& r2, uint32_t& r3, uint32_t addr) {
    asm volatile("ldmatrix.sync.aligned.m8n8.x4.shared.b16 {%0,%1,%2,%3}, [%4];"
                 : "=r"(r0), "=r"(r1), "=r"(r2), "=r"(r3) : "r"(addr));
}

__device__ __forceinline__ void cp_async16(void* smem_ptr, const void* gptr) {
    uint32_t s = (uint32_t)__cvta_generic_to_shared(smem_ptr);
    asm volatile("cp.async.cg.shared.global [%0], [%1], 16;" :: "r"(s), "l"(gptr));
}
#define CP_COMMIT()  asm volatile("cp.async.commit_group;")
#define CP_WAIT0()   asm volatile("cp.async.wait_group 0;")

// named barriers: producer arrives, consumer syncs
#define BAR_ARRIVE(id)  asm volatile("bar.arrive %0, 512;" :: "r"(id))
#define BAR_SYNC(id)    asm volatile("bar.sync %0, 512;" :: "r"(id) : "memory")
#define BAR_A_GROUP()   asm volatile("bar.sync 9, 256;" ::: "memory")
#define MEMBAR_CTA()    asm volatile("membar.cta;" ::: "memory")

__global__ __launch_bounds__(NTHR, 1)
void attn_fused_kernel(const float* __restrict__ q,
                       const float* __restrict__ k,
                       const float* __restrict__ v,
                       const float* __restrict__ sel,
                       const int* __restrict__ mask,
                       float* __restrict__ ctx,
                       float* __restrict__ attn)
{
    extern __shared__ float sm[];
    float (*Qs)[QS_STRIDE]    = (float (*)[QS_STRIDE])sm;                         // [64][68]
    float (*KV)[TK][QS_STRIDE]= (float (*)[TK][QS_STRIDE])(sm + TQ * QS_STRIDE);  // [2][64][68]
    float (*S)[S_STRIDE]      = (float (*)[S_STRIDE])(sm + TQ * QS_STRIDE + 2 * TK * QS_STRIDE); // [64][516]
    float* Rmax               = sm + TQ * QS_STRIDE + 2 * TK * QS_STRIDE + TQ * S_STRIDE;        // [64]
    float* Rinv               = Rmax + TQ;                                                        // [64]

    const int bh  = blockIdx.y;
    const int qt  = blockIdx.x;
    const int tid = threadIdx.x;
    const int warp = tid >> 5, lane = tid & 31;
    const int g  = lane >> 2;          // fragment group 0..7
    const int t  = lane & 3;           // fragment thread-in-group 0..3

    const float* qg = q + ((size_t)bh * LSEQ + (size_t)qt * TQ) * DH;
    const float* kg = k + (size_t)bh * LSEQ * DH;
    const float* vg = v + (size_t)bh * LSEQ * DH;

    const size_t base = (size_t)bh * LSEQ * LSEQ + (size_t)qt * TQ * LSEQ;
    const float* selp = sel + base;
    const int* mp = mask + base;
    float* attnp = attn + base;

    // shared-address bases for ldmatrix
    const uint32_t smem_u32 = (uint32_t)__cvta_generic_to_shared(sm);
    const uint32_t kv_u32   = smem_u32 + TQ * QS_STRIDE * 4;
    const uint32_t s_u32    = smem_u32 + (TQ * QS_STRIDE + 2 * TK * QS_STRIDE) * 4;

    // ---- prologue: async load Q tile + K tile 0 (all threads) ----
    #pragma unroll
    for (int i = tid; i < TQ * DH / 4; i += NTHR) {
        int e = i * 4, r = e >> 6, c = e & 63;
        cp_async16(&Qs[r][c], qg + e);
        cp_async16(&KV[0][r][c], kg + e);
    }
    CP_COMMIT();
    CP_WAIT0();
    __syncthreads();

    // =====================================================================
    // phase 1 (warp-specialized): A = warps 0..7 compute raw S = (Q*s)@K^T;
    //                             B = warps 8..15 stream sel/mask, finish S.
    // =====================================================================
    if (warp < 8) {
        // ---- group A: GEMM producer ----
        const int wm = warp & 3;           // rows wm*16..+15
        const int wn = warp >> 2;          // cols wn*32..+31 (4 nt sub-tiles)
        const int atid = tid;              // 0..255
        const uint32_t boff = (uint32_t)(((wn * 32 + (lane & 7)) * QS_STRIDE + 4 * (lane >> 3)) * 4);

        uint32_t qa[DH / 8][4];
        #pragma unroll
        for (int ks = 0; ks < DH / 8; ++ks) {
            const int k0 = ks * 8;
            qa[ks][0] = f2tf(0.125f * Qs[wm * 16 + g    ][k0 + t    ]);
            qa[ks][1] = f2tf(0.125f * Qs[wm * 16 + g + 8][k0 + t    ]);
            qa[ks][2] = f2tf(0.125f * Qs[wm * 16 + g    ][k0 + t + 4]);
            qa[ks][3] = f2tf(0.125f * Qs[wm * 16 + g + 8][k0 + t + 4]);
        }

        for (int kt = 0; kt < LSEQ / TK; ++kt) {
            if (kt > 0) {
                CP_WAIT0();
                BAR_A_GROUP();
            }
            if (kt + 1 < LSEQ / TK) {
                const float* kn = kg + (size_t)(kt + 1) * TK * DH;
                #pragma unroll
                for (int i = atid; i < TK * DH / 4; i += 256) {
                    int e = i * 4, r = e >> 6, c = e & 63;
                    cp_async16(&KV[(kt + 1) & 1][r][c], kn + e);
                }
                CP_COMMIT();
            }

            const uint32_t kbase = kv_u32 + (uint32_t)((kt & 1) * TK * QS_STRIDE * 4) + boff;
            float acc[4][4];
            #pragma unroll
            for (int nt = 0; nt < 4; ++nt)
                #pragma unroll
                for (int j = 0; j < 4; ++j) acc[nt][j] = 0.f;

            #pragma unroll
            for (int kb = 0; kb < 4; ++kb) {
                #pragma unroll
                for (int nt = 0; nt < 4; ++nt) {
                    uint32_t b0, b1, b2, b3;
                    ldsm_x4(b0, b1, b2, b3,
                            kbase + (uint32_t)((nt * 8 * QS_STRIDE + kb * 16) * 4));
                    uint32_t blo[2] = {f2tf_bits(b0), f2tf_bits(b1)};
                    uint32_t bhi[2] = {f2tf_bits(b2), f2tf_bits(b3)};
                    mma_tf32(acc[nt], qa[2 * kb    ], blo);
                    mma_tf32(acc[nt], qa[2 * kb + 1], bhi);
                }
            }

            #pragma unroll
            for (int nt = 0; nt < 4; ++nt) {
                const int n0 = kt * TK + wn * 32 + nt * 8 + 2 * t;
                *(float2*)&S[wm * 16 + g    ][n0] = make_float2(acc[nt][0], acc[nt][1]);
                *(float2*)&S[wm * 16 + g + 8][n0] = make_float2(acc[nt][2], acc[nt][3]);
            }
            MEMBAR_CTA();           // make STS visible before signaling B
            BAR_ARRIVE(1 + kt);     // tile kt ready for group B
        }

        // prefetch V tile 0 into buf 0 (overlaps B's tail + softmax exp pass)
        #pragma unroll
        for (int i = atid; i < TK * DH / 4; i += 256) {
            int e = i * 4, r = e >> 6, c = e & 63;
            cp_async16(&KV[0][r][c], vg + e);
        }
        CP_COMMIT();
    } else {
        // ---- group B: sel/mask streamer + masking consumer ----
        const int bw = warp - 8;           // 0..7 -> rows bw*8..+7
        float m[8];
        #pragma unroll
        for (int j = 0; j < 8; ++j) m[j] = -1e30f;

        for (int kt = 0; kt < LSEQ / TK; ++kt) {
            BAR_SYNC(1 + kt);              // wait for A's tile kt scores
            const int c = kt * TK + lane * 2;
            #pragma unroll
            for (int j = 0; j < 8; ++j) {
                const int r = bw * 8 + j;
                float2 sv = *(float2*)&S[r][c];
                float2 se = *(const float2*)&selp[(size_t)r * LSEQ + c];
                int2   mv = *(const int2*)  &mp  [(size_t)r * LSEQ + c];
                float x0 = mv.x ? sv.x + se.x : -1e12f;
                float x1 = mv.y ? sv.y + se.y : -1e12f;
                *(float2*)&S[r][c] = make_float2(x0, x1);
                m[j] = fmaxf(m[j], fmaxf(x0, x1));
            }
        }
        // warp-reduce row maxima, write Rmax
        #pragma unroll
        for (int j = 0; j < 8; ++j) {
            float mm = m[j];
            #pragma unroll
            for (int o = 16; o > 0; o >>= 1)
                mm = fmaxf(mm, __shfl_xor_sync(0xffffffffu, mm, o));
            if (lane == 0) Rmax[bw * 8 + j] = mm;
        }
    }
    __syncthreads();   // S (masked+biased) + Rmax complete; V tile0 in flight

    // ---- phase 2a (all warps): E = exp(x - max) into S (fp32), Rinv = 1/sum ----
    #pragma unroll
    for (int rr = 0; rr < 4; ++rr) {
        const int r = warp * 4 + rr;
        const float lmax = Rmax[r];
        float lsum = 0.f;
        #pragma unroll
        for (int i = 0; i < 4; ++i) {
            const int c = i * 128 + lane * 4;
            float4 sv = *(const float4*)&S[r][c];
            float4 e4;
            e4.x = __expf(sv.x - lmax);
            e4.y = __expf(sv.y - lmax);
            e4.z = __expf(sv.z - lmax);
            e4.w = __expf(sv.w - lmax);
            *(float4*)&S[r][c] = e4;
            lsum += (e4.x + e4.y) + (e4.z + e4.w);
        }
        #pragma unroll
        for (int o = 16; o > 0; o >>= 1)
            lsum += __shfl_xor_sync(0xffffffffu, lsum, o);
        if (lane == 0) Rinv[r] = 1.0f / lsum;
    }
    __syncthreads();   // E + Rinv visible to both groups

    // =====================================================================
    // phase 2b (warp-specialized): A = warps 0..7 PV GEMM (scale by Rinv at
    // the end); B = warps 8..15 stream attn = E * inv to global.
    // =====================================================================
    if (warp < 8) {
        // ---- group A: ctx = (E @ V) * inv ----
        const int wm = warp & 3;
        const int wn = warp >> 2;          // 2 groups x 32 cols
        const int atid = tid;              // 0..255
        const uint32_t aoff = (uint32_t)(((wm * 16 + (lane & 15)) * S_STRIDE + 4 * (lane >> 4)) * 4);

        float acc[4][4];
        #pragma unroll
        for (int nt = 0; nt < 4; ++nt)
            #pragma unroll
            for (int j = 0; j < 4; ++j) acc[nt][j] = 0.f;

        for (int vt = 0; vt < LSEQ / TK; ++vt) {
            CP_WAIT0();
            BAR_A_GROUP();
            if (vt + 1 < LSEQ / TK) {
                const float* vn = vg + (size_t)(vt + 1) * TK * DH;
                #pragma unroll
                for (int i = atid; i < TK * DH / 4; i += 256) {
                    int e = i * 4, r = e >> 6, c = e & 63;
                    cp_async16(&KV[(vt + 1) & 1][r][c], vn + e);
                }
                CP_COMMIT();
            }

            float (*Vs)[QS_STRIDE] = KV[vt & 1];
            #pragma unroll
            for (int ks = 0; ks < TK / 8; ++ks) {
                const int sk = vt * TK + ks * 8;   // S column (k index)
                const int vk = ks * 8;             // V smem row
                uint32_t a[4];                     // E fp32 -> cvt in regs
                ldsm_x4(a[0], a[1], a[2], a[3], s_u32 + aoff + (uint32_t)(sk * 4));
                a[0] = f2tf_bits(a[0]); a[1] = f2tf_bits(a[1]);
                a[2] = f2tf_bits(a[2]); a[3] = f2tf_bits(a[3]);
                #pragma unroll
                for (int nt = 0; nt < 4; ++nt) {
                    const int n0 = wn * 32 + nt * 8;
                    uint32_t b[2];
                    b[0] = f2tf(Vs[vk + t    ][n0 + g]);
                    b[1] = f2tf(Vs[vk + t + 4][n0 + g]);
                    mma_tf32(acc[nt], a, b);
                }
            }
            BAR_A_GROUP();   // buf[vt&1] free for prefetch at vt+1
        }

        const int r0 = wm * 16 + g;
        const int r1 = r0 + 8;
        const float inv0 = Rinv[r0];
        const float inv1 = Rinv[r1];
        float* cp = ctx + ((size_t)bh * LSEQ + (size_t)qt * TQ) * DH;
        #pragma unroll
        for (int nt = 0; nt < 4; ++nt) {
            const int n0 = wn * 32 + nt * 8 + 2 * t;
            *(float2*)&cp[(size_t)r0 * DH + n0] =
                make_float2(acc[nt][0] * inv0, acc[nt][1] * inv0);
            *(float2*)&cp[(size_t)r1 * DH + n0] =
                make_float2(acc[nt][2] * inv1, acc[nt][3] * inv1);
        }
    } else {
        // ---- group B: attn = E * inv, coalesced float4 stream ----
        const int bw = warp - 8;           // 0..7 -> rows bw*8..+7
        #pragma unroll
        for (int j = 0; j < 8; ++j) {
            const int r = bw * 8 + j;
            const float inv = Rinv[r];
            #pragma unroll
            for (int i = 0; i < 4; ++i) {
                const int c = i * 128 + lane * 4;
                float4 e4 = *(const float4*)&S[r][c];
                float4 a4;
                a4.x = e4.x * inv;
                a4.y = e4.y * inv;
                a4.z = e4.z * inv;
                a4.w = e4.w * inv;
                *(float4*)&attnp[(size_t)r * LSEQ + c] = a4;
            }
        }
    }
}

extern "C" void kernel_launch(void* const* d_in, const int* in_sizes, int n_in,
                              void* d_out, int out_size)
{
    (void)in_sizes; (void)n_in; (void)out_size;
    const float* q = (const float*)d_in[0];
    const float* k = (const float*)d_in[1];
    const float* v = (const float*)d_in[2];
    const float* sel = (const float*)d_in[3];
    const int* mask = (const int*)d_in[4];

    float* ctx  = (float*)d_out;                          // [128,512,64]
    float* attn = ctx + (size_t)BH * LSEQ * DH;           // [128,512,512]

    cudaFuncSetAttribute(attn_fused_kernel,
                         cudaFuncAttributeMaxDynamicSharedMemorySize, (int)SMEM_BYTES);

    dim3 grid(LSEQ / TQ, BH);   // (8, 128) = 1024 blocks
    attn_fused_kernel<<<grid, NTHR, SMEM_BYTES>>>(q, k, v, sel, mask, ctx, attn);
}